// round 16
// baseline (speedup 1.0000x reference)
#include <cuda_runtime.h>
#include <cuda_fp16.h>
#include <math_constants.h>
#include <cstdint>

#define DIM    1024
#define NHEAD  16
#define HDIM   64
#define BATCH  4
#define SEQ    2048
#define MTOT   (BATCH * SEQ)      // 8192

// Q pre-scale: 64^-0.5 * log2(e)  (softmax done in base 2)
#define QSCALE 0.18033688011112042f

// ---------------------------------------------------------------------------
// Scratch (fp16 activations/weights)
// ---------------------------------------------------------------------------
__device__ __half g_QKV[3 * MTOT * DIM];   // Q(pre-scaled),K,V
__device__ __half g_AO [MTOT * DIM];       // attention out
__device__ __half g_Xh [MTOT * DIM];       // fp16 x
__device__ __half g_Wh [4 * DIM * DIM];    // fp16 Wq,Wk,Wv,Wo

// ---------------------------------------------------------------------------
// Helpers
// ---------------------------------------------------------------------------
__device__ __forceinline__ float ex2f(float x) {
    float y;
    asm("ex2.approx.f32 %0, %1;" : "=f"(y) : "f"(x));
    return y;
}

__device__ __forceinline__ uint32_t smem_u32(const void* p) {
    uint32_t a;
    asm("{ .reg .u64 t; cvta.to.shared.u64 t, %1; cvt.u32.u64 %0, t; }"
        : "=r"(a) : "l"(p));
    return a;
}

__device__ __forceinline__ unsigned h2bits(__half2 h) {
    return *reinterpret_cast<unsigned*>(&h);
}

__device__ __forceinline__ void mma_f16(float* c,
                                        unsigned a0, unsigned a1,
                                        unsigned a2, unsigned a3,
                                        unsigned b0, unsigned b1) {
    asm volatile(
        "mma.sync.aligned.m16n8k16.row.col.f32.f16.f16.f32 "
        "{%0,%1,%2,%3},{%4,%5,%6,%7},{%8,%9},{%0,%1,%2,%3};\n"
        : "+f"(c[0]), "+f"(c[1]), "+f"(c[2]), "+f"(c[3])
        : "r"(a0), "r"(a1), "r"(a2), "r"(a3), "r"(b0), "r"(b1));
}

#define LDSM_X4(r0, r1, r2, r3, addr)                                         \
    asm volatile("ldmatrix.sync.aligned.m8n8.x4.shared.b16 {%0,%1,%2,%3}, [%4];" \
                 : "=r"(r0), "=r"(r1), "=r"(r2), "=r"(r3) : "r"(addr))

#define LDSM_X4T(r0, r1, r2, r3, addr)                                        \
    asm volatile("ldmatrix.sync.aligned.m8n8.x4.trans.shared.b16 {%0,%1,%2,%3}, [%4];" \
                 : "=r"(r0), "=r"(r1), "=r"(r2), "=r"(r3) : "r"(addr))

#define LDSM_X2T(r0, r1, addr)                                                \
    asm volatile("ldmatrix.sync.aligned.m8n8.x2.trans.shared.b16 {%0,%1}, [%2];" \
                 : "=r"(r0), "=r"(r1) : "r"(addr))

#define CP_ASYNC16(dst, src) \
    asm volatile("cp.async.cg.shared.global [%0], [%1], 16;" \
                 :: "r"(dst), "l"(src) : "memory")
#define CP_COMMIT() asm volatile("cp.async.commit_group;" ::: "memory")
#define CP_WAIT(N)  asm volatile("cp.async.wait_group %0;" :: "n"(N) : "memory")

// ---------------------------------------------------------------------------
// Fused pre-pass: fp32 -> fp16 for x AND the 4 weight matrices, MLP=4.
// ---------------------------------------------------------------------------
#define X4    (MTOT * DIM / 4)            // 2097152
#define SLAB4 (DIM * DIM / 4)             // 262144
#define TOT4  (X4 + 4 * SLAB4)            // 3145728

__global__ void cvt_all(const float4* __restrict__ x,
                        const float4* __restrict__ w0,
                        const float4* __restrict__ w1,
                        const float4* __restrict__ w2,
                        const float4* __restrict__ w3,
                        __half2* __restrict__ dx,
                        __half2* __restrict__ dw)
{
    const int stride = gridDim.x * blockDim.x;
    int i0 = blockIdx.x * blockDim.x + threadIdx.x;

    for (; i0 < TOT4; i0 += 4 * stride) {
        float4  v[4];
        __half2* dst[4];
        bool     ok[4];
        #pragma unroll
        for (int u = 0; u < 4; ++u) {
            int i = i0 + u * stride;
            ok[u] = (i < TOT4);
            if (ok[u]) {
                if (i < X4) {
                    v[u]   = x[i];
                    dst[u] = dx + 2 * (size_t)i;
                } else {
                    int k    = i - X4;
                    int slab = k / SLAB4;
                    int j    = k - slab * SLAB4;
                    const float4* s = (slab == 0) ? w0 : (slab == 1) ? w1
                                     : (slab == 2) ? w2 : w3;
                    v[u]   = s[j];
                    dst[u] = dw + (size_t)slab * (2 * SLAB4) + 2 * (size_t)j;
                }
            }
        }
        #pragma unroll
        for (int u = 0; u < 4; ++u) {
            if (ok[u]) {
                dst[u][0] = __floats2half2_rn(v[u].x, v[u].y);
                dst[u][1] = __floats2half2_rn(v[u].z, v[u].w);
            }
        }
    }
}

// ---------------------------------------------------------------------------
// FP16 GEMM: C = A * W^T. Tile 128(M) x 128(N), BK=64, 3-stage cp.async.
// 256 threads / 8 warps, warp tile 32x64, 2 blocks/SM.
// ---------------------------------------------------------------------------
#define BK      64
#define NCH     (DIM / BK)              // 16
#define GROWB   144
#define A_STGB  (128 * GROWB)           // 18432
#define STGB    (2 * A_STGB)            // 36864 (A + B)
#define SMEM_GEMM (3 * STGB)            // 110592

template<bool HALF_OUT, bool SCALEQ>
__global__ __launch_bounds__(256, 2)
void gemm_f16(const __half* __restrict__ Abase,
              const __half* __restrict__ Wbase,
              void* __restrict__ Cvoid)
{
    extern __shared__ char smc[];
    const uint32_t sbase = smem_u32(smc);

    const int tid  = threadIdx.x;
    const int lane = tid & 31;
    const int warp = tid >> 5;           // 0..7
    const int wm   = warp & 3;           // m offset wm*32
    const int wn   = warp >> 2;          // n offset wn*64
    const int r    = lane >> 2;
    const int t    = lane & 3;
    const int m0   = blockIdx.y * 128;
    const int n0   = blockIdx.x * 128;

    const __half* A = Abase;
    const __half* W = Wbase + (size_t)blockIdx.z * DIM * DIM;

    float c[2][8][4];
    #pragma unroll
    for (int mi = 0; mi < 2; ++mi)
        #pragma unroll
        for (int ni = 0; ni < 8; ++ni)
            #pragma unroll
            for (int j = 0; j < 4; ++j) c[mi][ni][j] = 0.0f;

    const int arow  = ((lane >> 3) & 1) * 8 + (lane & 7);
    const int abyte = (lane >> 4) * 16;
    const int brow  = ((lane >> 4) & 1) * 8 + (lane & 7);
    const int bbyte = ((lane >> 3) & 1) * 16;
    const uint32_t aFrag = (uint32_t)((wm * 32 + arow) * GROWB + abyte);
    const uint32_t bFrag = (uint32_t)(A_STGB + (wn * 64 + brow) * GROWB + bbyte);

    auto load_stage = [&](int ch, int s) {
        const __half* Ab = A + (size_t)m0 * DIM + ch * BK;
        const __half* Wb = W + (size_t)n0 * DIM + ch * BK;
        const uint32_t as = sbase + s * STGB;
        const uint32_t bs = as + A_STGB;
        #pragma unroll
        for (int p = 0; p < 4; ++p) {             // A: 1024 x 16B
            int slot = tid + p * 256;
            int row  = slot >> 3;
            int c8   = (slot & 7) * 8;
            CP_ASYNC16(as + row * GROWB + c8 * 2,
                       Ab + (size_t)row * DIM + c8);
        }
        #pragma unroll
        for (int p = 0; p < 4; ++p) {             // B: 1024 x 16B
            int slot = tid + p * 256;
            int row  = slot >> 3;
            int c8   = (slot & 7) * 8;
            CP_ASYNC16(bs + row * GROWB + c8 * 2,
                       Wb + (size_t)row * DIM + c8);
        }
        CP_COMMIT();
    };

    load_stage(0, 0);
    load_stage(1, 1);

    for (int ch = 0; ch < NCH; ++ch) {
        if (ch < NCH - 1) { CP_WAIT(1); } else { CP_WAIT(0); }
        __syncthreads();
        if (ch + 2 < NCH) load_stage(ch + 2, (ch + 2) % 3);

        const uint32_t stg = sbase + (ch % 3) * STGB;
        const uint32_t aB  = stg + aFrag;
        const uint32_t bB  = stg + bFrag;

        #pragma unroll
        for (int ks = 0; ks < 4; ++ks) {
            unsigned a[2][4], b[4][4];
            #pragma unroll
            for (int mi = 0; mi < 2; ++mi)
                LDSM_X4(a[mi][0], a[mi][1], a[mi][2], a[mi][3],
                        aB + mi * (16 * GROWB) + ks * 32);
            #pragma unroll
            for (int pi = 0; pi < 4; ++pi)
                LDSM_X4(b[pi][0], b[pi][1], b[pi][2], b[pi][3],
                        bB + pi * (16 * GROWB) + ks * 32);
            #pragma unroll
            for (int mi = 0; mi < 2; ++mi)
                #pragma unroll
                for (int pi = 0; pi < 4; ++pi) {
                    mma_f16(c[mi][2*pi],   a[mi][0], a[mi][1], a[mi][2], a[mi][3],
                            b[pi][0], b[pi][1]);
                    mma_f16(c[mi][2*pi+1], a[mi][0], a[mi][1], a[mi][2], a[mi][3],
                            b[pi][2], b[pi][3]);
                }
        }
    }

    const float sc = (SCALEQ && blockIdx.z == 0) ? QSCALE : 1.0f;
    #pragma unroll
    for (int mi = 0; mi < 2; ++mi) {
        #pragma unroll
        for (int ni = 0; ni < 8; ++ni) {
            int row = m0 + wm * 32 + mi * 16 + r;
            int col = n0 + wn * 64 + ni * 8 + 2 * t;
            float v0 = c[mi][ni][0] * sc, v1 = c[mi][ni][1] * sc;
            float v2 = c[mi][ni][2] * sc, v3 = c[mi][ni][3] * sc;
            if (HALF_OUT) {
                __half* C = (__half*)Cvoid + (size_t)blockIdx.z * MTOT * DIM;
                *reinterpret_cast<__half2*>(&C[(size_t)row * DIM + col]) =
                    __floats2half2_rn(v0, v1);
                *reinterpret_cast<__half2*>(&C[(size_t)(row + 8) * DIM + col]) =
                    __floats2half2_rn(v2, v3);
            } else {
                float* C = (float*)Cvoid;
                *reinterpret_cast<float2*>(&C[(size_t)row * DIM + col])       = make_float2(v0, v1);
                *reinterpret_cast<float2*>(&C[(size_t)(row + 8) * DIM + col]) = make_float2(v2, v3);
            }
        }
    }
}

// ---------------------------------------------------------------------------
// Flash attention, fp16, register-resident P.
// Q-tile 64 (4 warps / 128 threads), K-tile 64, K/V double-buffered cp.async.
// l via tensor core (ones-block in V row padding). p = 2^(s-m) computed in
// f16x2 (h2exp2): MUFU count halved vs fp32 ex2; no unpacks needed since the
// row-sum comes from the P*1 mma.
// ---------------------------------------------------------------------------
#define FROWB 144                               // 64 halves + 16B pad (= ones)
#define QS_B  0
#define KS_B(s) (9216 + (s) * 9216)
#define VS_B(s) (27648 + (s) * 9216)
#define FL_SMEMB 46080

__global__ __launch_bounds__(128, 4)
void flash_f16(const __half* __restrict__ Q,
               const __half* __restrict__ K,
               const __half* __restrict__ V,
               __half* __restrict__ O)
{
    extern __shared__ char smc[];
    const uint32_t smb = smem_u32(smc);

    const int tid  = threadIdx.x;
    const int lane = tid & 31;
    const int warp = tid >> 5;            // 0..3
    const int r    = lane >> 2;
    const int t    = lane & 3;
    const int qt   = (gridDim.x - 1) - blockIdx.x;   // heavy first
    const int h    = blockIdx.y;
    const int b    = blockIdx.z;
    const int q0   = qt * 64;
    const size_t base = (size_t)b * SEQ * DIM + (size_t)h * HDIM;

    const int arow  = ((lane >> 3) & 1) * 8 + (lane & 7);
    const int abyte = (lane >> 4) * 16;
    const int brow  = ((lane >> 4) & 1) * 8 + (lane & 7);
    const int bbyte = ((lane >> 3) & 1) * 16;
    const uint32_t qFrag = smb + QS_B + (warp * 16 + arow) * FROWB + abyte;

    // per-buffer fragment bases (hoisted out of the main loop)
    uint32_t kF[2], vF[2], vS[2];
    #pragma unroll
    for (int s = 0; s < 2; ++s) {
        kF[s] = smb + KS_B(s) + brow * FROWB + bbyte;
        vF[s] = smb + VS_B(s) + arow * FROWB + abyte;
        vS[s] = smb + VS_B(s) + (lane & 15) * FROWB + 128;   // ones column block
    }

    auto load_kv = [&](int kt, int s) {
        const __half* Kb = K + base + (size_t)(kt * 64) * DIM;
        const __half* Vb = V + base + (size_t)(kt * 64) * DIM;
        const uint32_t ks = smb + KS_B(s);
        const uint32_t vs = smb + VS_B(s);
        #pragma unroll
        for (int p = 0; p < 4; ++p) {             // 512 x 16B each tile
            int slot = tid + p * 128;
            int row  = slot >> 3;
            int c8   = (slot & 7) * 8;
            CP_ASYNC16(ks + row * FROWB + c8 * 2, Kb + (size_t)row * DIM + c8);
            CP_ASYNC16(vs + row * FROWB + c8 * 2, Vb + (size_t)row * DIM + c8);
        }
        CP_COMMIT();
    };

    load_kv(0, 0);

    // Q tile: 64 rows x 8 chunks = 512 slots (4/thread)
    #pragma unroll
    for (int p = 0; p < 4; ++p) {
        int slot = tid + p * 128;
        int row  = slot >> 3;
        int c8   = (slot & 7) * 8;
        uint4 v = *reinterpret_cast<const uint4*>(
            &Q[base + (size_t)(q0 + row) * DIM + c8]);
        *reinterpret_cast<uint4*>(smc + QS_B + row * FROWB + c8 * 2) = v;
    }

    // Initialize ones-blocks in both V buffers' row padding (cp.async never
    // touches bytes 128..143 of a row, so these persist across reloads).
    {
        int row = tid & 63;
        int s   = tid >> 6;
        uint4 ones = make_uint4(0x3C003C00u, 0x3C003C00u, 0x3C003C00u, 0x3C003C00u);
        *reinterpret_cast<uint4*>(smc + VS_B(s) + row * FROWB + 128) = ones;
    }
    __syncthreads();

    unsigned qa[4][4];
    #pragma unroll
    for (int ks = 0; ks < 4; ++ks)
        LDSM_X4(qa[ks][0], qa[ks][1], qa[ks][2], qa[ks][3], qFrag + ks * 32);

    float m_i[2] = {-CUDART_INF_F, -CUDART_INF_F};
    float osum[4] = {0.0f, 0.0f, 0.0f, 0.0f};   // l accumulators via P*1 mma
    float o[8][4];
    #pragma unroll
    for (int ni = 0; ni < 8; ++ni)
        #pragma unroll
        for (int j = 0; j < 4; ++j) o[ni][j] = 0.0f;

    const int row_loc = warp * 16 + r;
    const int ktmax   = qt;               // 64-row q-tile == 64-row kv-tile

    for (int kt = 0; kt <= ktmax; ++kt) {
        const int s  = kt & 1;
        const int k0 = kt * 64;

        CP_WAIT(0);
        __syncthreads();
        if (kt < ktmax) load_kv(kt + 1, s ^ 1);

        // ---- S = Q K^T ----
        float sreg[8][4];
        #pragma unroll
        for (int ni = 0; ni < 8; ++ni)
            #pragma unroll
            for (int j = 0; j < 4; ++j) sreg[ni][j] = 0.0f;

        #pragma unroll
        for (int ks = 0; ks < 4; ++ks) {
            #pragma unroll
            for (int pi = 0; pi < 4; ++pi) {
                unsigned b0, b1, b2, b3;
                LDSM_X4(b0, b1, b2, b3, kF[s] + pi * (16 * FROWB) + ks * 32);
                mma_f16(sreg[2*pi],   qa[ks][0], qa[ks][1], qa[ks][2], qa[ks][3], b0, b1);
                mma_f16(sreg[2*pi+1], qa[ks][0], qa[ks][1], qa[ks][2], qa[ks][3], b2, b3);
            }
        }

        // ---- causal mask (diagonal tile only) ----
        if (kt == ktmax) {
            const int rg0 = q0 + row_loc;
            #pragma unroll
            for (int ni = 0; ni < 8; ++ni) {
                int cg = k0 + ni * 8 + 2 * t;
                if (cg     > rg0    ) sreg[ni][0] = -CUDART_INF_F;
                if (cg + 1 > rg0    ) sreg[ni][1] = -CUDART_INF_F;
                if (cg     > rg0 + 8) sreg[ni][2] = -CUDART_INF_F;
                if (cg + 1 > rg0 + 8) sreg[ni][3] = -CUDART_INF_F;
            }
        }

        // ---- running max + rescale (fp32) ----
        float mnew[2], alpha[2];
        #pragma unroll
        for (int hh = 0; hh < 2; ++hh) {
            float mx = -CUDART_INF_F;
            #pragma unroll
            for (int ni = 0; ni < 8; ++ni)
                mx = fmaxf(mx, fmaxf(sreg[ni][hh * 2], sreg[ni][hh * 2 + 1]));
            mx = fmaxf(mx, __shfl_xor_sync(0xffffffffu, mx, 1, 4));
            mx = fmaxf(mx, __shfl_xor_sync(0xffffffffu, mx, 2, 4));
            mnew[hh]  = fmaxf(m_i[hh], mx);
            alpha[hh] = ex2f(m_i[hh] - mnew[hh]);
            m_i[hh]   = mnew[hh];
            #pragma unroll
            for (int ni = 0; ni < 8; ++ni) {
                o[ni][hh * 2]     *= alpha[hh];
                o[ni][hh * 2 + 1] *= alpha[hh];
            }
        }
        osum[0] *= alpha[0]; osum[1] *= alpha[0];
        osum[2] *= alpha[1]; osum[3] *= alpha[1];

        // ---- p = 2^(s-m) computed in f16x2 -> A-fragments directly ----
        // (MUFU halved vs fp32 ex2; no unpacks since l comes from P*1 mma)
        unsigned pa[4][4];
        #pragma unroll
        for (int ks = 0; ks < 4; ++ks) {
            #pragma unroll
            for (int half = 0; half < 2; ++half) {
                int ni = 2 * ks + half;
                __half2 e01 = h2exp2(__floats2half2_rn(
                    sreg[ni][0] - mnew[0], sreg[ni][1] - mnew[0]));
                __half2 e23 = h2exp2(__floats2half2_rn(
                    sreg[ni][2] - mnew[1], sreg[ni][3] - mnew[1]));
                pa[ks][2 * half]     = h2bits(e01);
                pa[ks][2 * half + 1] = h2bits(e23);
            }
        }

        // ---- O += P V, and osum += P * ones (l via tensor core) ----
        #pragma unroll
        for (int ks = 0; ks < 4; ++ks) {
            #pragma unroll
            for (int pi = 0; pi < 4; ++pi) {
                unsigned b0, b1, b2, b3;
                LDSM_X4T(b0, b1, b2, b3,
                         vF[s] + ks * (16 * FROWB) + pi * 32);
                mma_f16(o[2*pi],   pa[ks][0], pa[ks][1], pa[ks][2], pa[ks][3], b0, b1);
                mma_f16(o[2*pi+1], pa[ks][0], pa[ks][1], pa[ks][2], pa[ks][3], b2, b3);
            }
            unsigned sb0, sb1;
            LDSM_X2T(sb0, sb1, vS[s] + ks * (16 * FROWB));
            mma_f16(osum, pa[ks][0], pa[ks][1], pa[ks][2], pa[ks][3], sb0, sb1);
        }
        // no tail barrier: next iteration's top-of-loop sync provides ordering
    }

    // ---- normalize + fp16 store (l = osum; all cols of ones-block equal) ----
    const float inv_l0 = 1.0f / osum[0];
    const float inv_l1 = 1.0f / osum[2];
    #pragma unroll
    for (int hh = 0; hh < 2; ++hh) {
        float inv_l = (hh == 0) ? inv_l0 : inv_l1;
        int row = q0 + row_loc + hh * 8;
        #pragma unroll
        for (int ni = 0; ni < 8; ++ni) {
            *reinterpret_cast<__half2*>(
                &O[base + (size_t)row * DIM + ni * 8 + 2 * t]) =
                __floats2half2_rn(o[ni][hh * 2] * inv_l, o[ni][hh * 2 + 1] * inv_l);
        }
    }
}

// ---------------------------------------------------------------------------
// Launch
// ---------------------------------------------------------------------------
extern "C" void kernel_launch(void* const* d_in, const int* in_sizes, int n_in,
                              void* d_out, int out_size)
{
    const float* x  = (const float*)d_in[0];
    const float* Wq = (const float*)d_in[2];
    const float* Wk = (const float*)d_in[3];
    const float* Wv = (const float*)d_in[4];
    const float* Wo = (const float*)d_in[5];
    float* out = (float*)d_out;

    __half *QKV, *AOd, *Xh, *Wh;
    cudaGetSymbolAddress((void**)&QKV, g_QKV);
    cudaGetSymbolAddress((void**)&AOd, g_AO);
    cudaGetSymbolAddress((void**)&Xh,  g_Xh);
    cudaGetSymbolAddress((void**)&Wh,  g_Wh);

    static bool attr_set = false;
    if (!attr_set) {
        cudaFuncSetAttribute(flash_f16,
                             cudaFuncAttributeMaxDynamicSharedMemorySize, FL_SMEMB);
        cudaFuncSetAttribute((gemm_f16<true, true>),
                             cudaFuncAttributeMaxDynamicSharedMemorySize, SMEM_GEMM);
        cudaFuncSetAttribute((gemm_f16<false, false>),
                             cudaFuncAttributeMaxDynamicSharedMemorySize, SMEM_GEMM);
        attr_set = true;
    }

    // fused fp32->fp16 conversion of x + all weights, MLP=4
    cvt_all<<<1184, 256>>>((const float4*)x,
                           (const float4*)Wq, (const float4*)Wk,
                           (const float4*)Wv, (const float4*)Wo,
                           (__half2*)Xh, (__half2*)Wh);

    // fused Q,K,V projections; Q pre-scaled by 0.125*log2(e)
    dim3 gQKV(DIM / 128, MTOT / 128, 3);   // (8, 64, 3)
    gemm_f16<true, true><<<gQKV, 256, SMEM_GEMM>>>(Xh, Wh, QKV);

    const __half* Qd = QKV;
    const __half* Kd = QKV + (size_t)MTOT * DIM;
    const __half* Vd = QKV + 2 * (size_t)MTOT * DIM;

    dim3 gF(SEQ / 64, NHEAD, BATCH);       // (32, 16, 4)
    flash_f16<<<gF, 128, FL_SMEMB>>>(Qd, Kd, Vd, AOd);

    dim3 gO(DIM / 128, MTOT / 128, 1);     // (8, 64, 1)
    gemm_f16<false, false><<<gO, 256, SMEM_GEMM>>>(AOd, Wh + 3 * (size_t)DIM * DIM, out);
}

// round 17
// speedup vs baseline: 1.0001x; 1.0001x over previous
#include <cuda_runtime.h>
#include <cuda_fp16.h>
#include <math_constants.h>
#include <cstdint>

#define DIM    1024
#define NHEAD  16
#define HDIM   64
#define BATCH  4
#define SEQ    2048
#define MTOT   (BATCH * SEQ)      // 8192

// Q pre-scale: 64^-0.5 * log2(e)  (softmax done in base 2)
#define QSCALE 0.18033688011112042f

// ---------------------------------------------------------------------------
// Scratch (fp16 activations/weights)
// ---------------------------------------------------------------------------
__device__ __half g_QKV[3 * MTOT * DIM];   // Q(pre-scaled),K,V
__device__ __half g_AO [MTOT * DIM];       // attention out
__device__ __half g_Xh [MTOT * DIM];       // fp16 x
__device__ __half g_Wh [4 * DIM * DIM];    // fp16 Wq,Wk,Wv,Wo

// ---------------------------------------------------------------------------
// Helpers
// ---------------------------------------------------------------------------
__device__ __forceinline__ float ex2f(float x) {
    float y;
    asm("ex2.approx.f32 %0, %1;" : "=f"(y) : "f"(x));
    return y;
}

__device__ __forceinline__ uint32_t smem_u32(const void* p) {
    uint32_t a;
    asm("{ .reg .u64 t; cvta.to.shared.u64 t, %1; cvt.u32.u64 %0, t; }"
        : "=r"(a) : "l"(p));
    return a;
}

__device__ __forceinline__ unsigned pack_h2(float lo, float hi) {
    __half2 h = __floats2half2_rn(lo, hi);
    return *reinterpret_cast<unsigned*>(&h);
}

__device__ __forceinline__ void mma_f16(float* c,
                                        unsigned a0, unsigned a1,
                                        unsigned a2, unsigned a3,
                                        unsigned b0, unsigned b1) {
    asm volatile(
        "mma.sync.aligned.m16n8k16.row.col.f32.f16.f16.f32 "
        "{%0,%1,%2,%3},{%4,%5,%6,%7},{%8,%9},{%0,%1,%2,%3};\n"
        : "+f"(c[0]), "+f"(c[1]), "+f"(c[2]), "+f"(c[3])
        : "r"(a0), "r"(a1), "r"(a2), "r"(a3), "r"(b0), "r"(b1));
}

#define LDSM_X4(r0, r1, r2, r3, addr)                                         \
    asm volatile("ldmatrix.sync.aligned.m8n8.x4.shared.b16 {%0,%1,%2,%3}, [%4];" \
                 : "=r"(r0), "=r"(r1), "=r"(r2), "=r"(r3) : "r"(addr))

#define LDSM_X4T(r0, r1, r2, r3, addr)                                        \
    asm volatile("ldmatrix.sync.aligned.m8n8.x4.trans.shared.b16 {%0,%1,%2,%3}, [%4];" \
                 : "=r"(r0), "=r"(r1), "=r"(r2), "=r"(r3) : "r"(addr))

#define LDSM_X2T(r0, r1, addr)                                                \
    asm volatile("ldmatrix.sync.aligned.m8n8.x2.trans.shared.b16 {%0,%1}, [%2];" \
                 : "=r"(r0), "=r"(r1) : "r"(addr))

#define CP_ASYNC16(dst, src) \
    asm volatile("cp.async.cg.shared.global [%0], [%1], 16;" \
                 :: "r"(dst), "l"(src) : "memory")
#define CP_COMMIT() asm volatile("cp.async.commit_group;" ::: "memory")
#define CP_WAIT(N)  asm volatile("cp.async.wait_group %0;" :: "n"(N) : "memory")

// ---------------------------------------------------------------------------
// Fused pre-pass: fp32 -> fp16 for x AND the 4 weight matrices, MLP=4.
// Grid 1536 x 256: 4*stride = 1572864 divides TOT4 exactly (x2) -> no
// bounds checks, every thread does exactly 2 full MLP-4 batches.
// ---------------------------------------------------------------------------
#define X4    (MTOT * DIM / 4)            // 2097152
#define SLAB4 (DIM * DIM / 4)             // 262144
#define TOT4  (X4 + 4 * SLAB4)            // 3145728

__global__ void cvt_all(const float4* __restrict__ x,
                        const float4* __restrict__ w0,
                        const float4* __restrict__ w1,
                        const float4* __restrict__ w2,
                        const float4* __restrict__ w3,
                        __half2* __restrict__ dx,
                        __half2* __restrict__ dw)
{
    const int stride = gridDim.x * blockDim.x;        // 393216
    int i0 = blockIdx.x * blockDim.x + threadIdx.x;

    #pragma unroll
    for (int rep = 0; rep < 2; ++rep) {
        float4   v[4];
        __half2* dst[4];
        #pragma unroll
        for (int u = 0; u < 4; ++u) {
            int i = i0 + u * stride;
            if (i < X4) {
                v[u]   = x[i];
                dst[u] = dx + 2 * (size_t)i;
            } else {
                int k    = i - X4;
                int slab = k / SLAB4;
                int j    = k - slab * SLAB4;
                const float4* s = (slab == 0) ? w0 : (slab == 1) ? w1
                                 : (slab == 2) ? w2 : w3;
                v[u]   = s[j];
                dst[u] = dw + (size_t)slab * (2 * SLAB4) + 2 * (size_t)j;
            }
        }
        #pragma unroll
        for (int u = 0; u < 4; ++u) {
            dst[u][0] = __floats2half2_rn(v[u].x, v[u].y);
            dst[u][1] = __floats2half2_rn(v[u].z, v[u].w);
        }
        i0 += 4 * stride;
    }
}

// ---------------------------------------------------------------------------
// FP16 GEMM: C = A * W^T. Tile 128(M) x 128(N), BK=64, 3-stage cp.async.
// 256 threads / 8 warps, warp tile 32x64, 2 blocks/SM.
// ---------------------------------------------------------------------------
#define BK      64
#define NCH     (DIM / BK)              // 16
#define GROWB   144
#define A_STGB  (128 * GROWB)           // 18432
#define STGB    (2 * A_STGB)            // 36864 (A + B)
#define SMEM_GEMM (3 * STGB)            // 110592

template<bool HALF_OUT, bool SCALEQ>
__global__ __launch_bounds__(256, 2)
void gemm_f16(const __half* __restrict__ Abase,
              const __half* __restrict__ Wbase,
              void* __restrict__ Cvoid)
{
    extern __shared__ char smc[];
    const uint32_t sbase = smem_u32(smc);

    const int tid  = threadIdx.x;
    const int lane = tid & 31;
    const int warp = tid >> 5;           // 0..7
    const int wm   = warp & 3;           // m offset wm*32
    const int wn   = warp >> 2;          // n offset wn*64
    const int r    = lane >> 2;
    const int t    = lane & 3;
    const int m0   = blockIdx.y * 128;
    const int n0   = blockIdx.x * 128;

    const __half* A = Abase;
    const __half* W = Wbase + (size_t)blockIdx.z * DIM * DIM;

    float c[2][8][4];
    #pragma unroll
    for (int mi = 0; mi < 2; ++mi)
        #pragma unroll
        for (int ni = 0; ni < 8; ++ni)
            #pragma unroll
            for (int j = 0; j < 4; ++j) c[mi][ni][j] = 0.0f;

    const int arow  = ((lane >> 3) & 1) * 8 + (lane & 7);
    const int abyte = (lane >> 4) * 16;
    const int brow  = ((lane >> 4) & 1) * 8 + (lane & 7);
    const int bbyte = ((lane >> 3) & 1) * 16;
    const uint32_t aFrag = (uint32_t)((wm * 32 + arow) * GROWB + abyte);
    const uint32_t bFrag = (uint32_t)(A_STGB + (wn * 64 + brow) * GROWB + bbyte);

    auto load_stage = [&](int ch, int s) {
        const __half* Ab = A + (size_t)m0 * DIM + ch * BK;
        const __half* Wb = W + (size_t)n0 * DIM + ch * BK;
        const uint32_t as = sbase + s * STGB;
        const uint32_t bs = as + A_STGB;
        #pragma unroll
        for (int p = 0; p < 4; ++p) {             // A: 1024 x 16B
            int slot = tid + p * 256;
            int row  = slot >> 3;
            int c8   = (slot & 7) * 8;
            CP_ASYNC16(as + row * GROWB + c8 * 2,
                       Ab + (size_t)row * DIM + c8);
        }
        #pragma unroll
        for (int p = 0; p < 4; ++p) {             // B: 1024 x 16B
            int slot = tid + p * 256;
            int row  = slot >> 3;
            int c8   = (slot & 7) * 8;
            CP_ASYNC16(bs + row * GROWB + c8 * 2,
                       Wb + (size_t)row * DIM + c8);
        }
        CP_COMMIT();
    };

    load_stage(0, 0);
    load_stage(1, 1);

    for (int ch = 0; ch < NCH; ++ch) {
        if (ch < NCH - 1) { CP_WAIT(1); } else { CP_WAIT(0); }
        __syncthreads();
        if (ch + 2 < NCH) load_stage(ch + 2, (ch + 2) % 3);

        const uint32_t stg = sbase + (ch % 3) * STGB;
        const uint32_t aB  = stg + aFrag;
        const uint32_t bB  = stg + bFrag;

        #pragma unroll
        for (int ks = 0; ks < 4; ++ks) {
            unsigned a[2][4], b[4][4];
            #pragma unroll
            for (int mi = 0; mi < 2; ++mi)
                LDSM_X4(a[mi][0], a[mi][1], a[mi][2], a[mi][3],
                        aB + mi * (16 * GROWB) + ks * 32);
            #pragma unroll
            for (int pi = 0; pi < 4; ++pi)
                LDSM_X4(b[pi][0], b[pi][1], b[pi][2], b[pi][3],
                        bB + pi * (16 * GROWB) + ks * 32);
            #pragma unroll
            for (int mi = 0; mi < 2; ++mi)
                #pragma unroll
                for (int pi = 0; pi < 4; ++pi) {
                    mma_f16(c[mi][2*pi],   a[mi][0], a[mi][1], a[mi][2], a[mi][3],
                            b[pi][0], b[pi][1]);
                    mma_f16(c[mi][2*pi+1], a[mi][0], a[mi][1], a[mi][2], a[mi][3],
                            b[pi][2], b[pi][3]);
                }
        }
    }

    const float sc = (SCALEQ && blockIdx.z == 0) ? QSCALE : 1.0f;
    #pragma unroll
    for (int mi = 0; mi < 2; ++mi) {
        #pragma unroll
        for (int ni = 0; ni < 8; ++ni) {
            int row = m0 + wm * 32 + mi * 16 + r;
            int col = n0 + wn * 64 + ni * 8 + 2 * t;
            float v0 = c[mi][ni][0] * sc, v1 = c[mi][ni][1] * sc;
            float v2 = c[mi][ni][2] * sc, v3 = c[mi][ni][3] * sc;
            if (HALF_OUT) {
                __half* C = (__half*)Cvoid + (size_t)blockIdx.z * MTOT * DIM;
                *reinterpret_cast<__half2*>(&C[(size_t)row * DIM + col]) =
                    __floats2half2_rn(v0, v1);
                *reinterpret_cast<__half2*>(&C[(size_t)(row + 8) * DIM + col]) =
                    __floats2half2_rn(v2, v3);
            } else {
                float* C = (float*)Cvoid;
                *reinterpret_cast<float2*>(&C[(size_t)row * DIM + col])       = make_float2(v0, v1);
                *reinterpret_cast<float2*>(&C[(size_t)(row + 8) * DIM + col]) = make_float2(v2, v3);
            }
        }
    }
}

// ---------------------------------------------------------------------------
// Flash attention, fp16, register-resident P, fp32-ex2 softmax (best-measured).
// Q-tile 64 (4 warps / 128 threads), K-tile 64, K/V double-buffered cp.async.
// l via tensor core (ones-block in V row padding).
// ---------------------------------------------------------------------------
#define FROWB 144                               // 64 halves + 16B pad (= ones)
#define QS_B  0
#define KS_B(s) (9216 + (s) * 9216)
#define VS_B(s) (27648 + (s) * 9216)
#define FL_SMEMB 46080

__global__ __launch_bounds__(128, 4)
void flash_f16(const __half* __restrict__ Q,
               const __half* __restrict__ K,
               const __half* __restrict__ V,
               __half* __restrict__ O)
{
    extern __shared__ char smc[];
    const uint32_t smb = smem_u32(smc);

    const int tid  = threadIdx.x;
    const int lane = tid & 31;
    const int warp = tid >> 5;            // 0..3
    const int r    = lane >> 2;
    const int t    = lane & 3;
    const int qt   = (gridDim.x - 1) - blockIdx.x;   // heavy first
    const int h    = blockIdx.y;
    const int b    = blockIdx.z;
    const int q0   = qt * 64;
    const size_t base = (size_t)b * SEQ * DIM + (size_t)h * HDIM;

    const int arow  = ((lane >> 3) & 1) * 8 + (lane & 7);
    const int abyte = (lane >> 4) * 16;
    const int brow  = ((lane >> 4) & 1) * 8 + (lane & 7);
    const int bbyte = ((lane >> 3) & 1) * 16;
    const uint32_t qFrag = smb + QS_B + (warp * 16 + arow) * FROWB + abyte;

    // per-buffer fragment bases (hoisted out of the main loop)
    uint32_t kF[2], vF[2], vS[2];
    #pragma unroll
    for (int s = 0; s < 2; ++s) {
        kF[s] = smb + KS_B(s) + brow * FROWB + bbyte;
        vF[s] = smb + VS_B(s) + arow * FROWB + abyte;
        vS[s] = smb + VS_B(s) + (lane & 15) * FROWB + 128;   // ones column block
    }

    auto load_kv = [&](int kt, int s) {
        const __half* Kb = K + base + (size_t)(kt * 64) * DIM;
        const __half* Vb = V + base + (size_t)(kt * 64) * DIM;
        const uint32_t ks = smb + KS_B(s);
        const uint32_t vs = smb + VS_B(s);
        #pragma unroll
        for (int p = 0; p < 4; ++p) {             // 512 x 16B each tile
            int slot = tid + p * 128;
            int row  = slot >> 3;
            int c8   = (slot & 7) * 8;
            CP_ASYNC16(ks + row * FROWB + c8 * 2, Kb + (size_t)row * DIM + c8);
            CP_ASYNC16(vs + row * FROWB + c8 * 2, Vb + (size_t)row * DIM + c8);
        }
        CP_COMMIT();
    };

    load_kv(0, 0);

    // Q tile: 64 rows x 8 chunks = 512 slots (4/thread)
    #pragma unroll
    for (int p = 0; p < 4; ++p) {
        int slot = tid + p * 128;
        int row  = slot >> 3;
        int c8   = (slot & 7) * 8;
        uint4 v = *reinterpret_cast<const uint4*>(
            &Q[base + (size_t)(q0 + row) * DIM + c8]);
        *reinterpret_cast<uint4*>(smc + QS_B + row * FROWB + c8 * 2) = v;
    }

    // Initialize ones-blocks in both V buffers' row padding (cp.async never
    // touches bytes 128..143 of a row, so these persist across reloads).
    {
        int row = tid & 63;
        int s   = tid >> 6;
        uint4 ones = make_uint4(0x3C003C00u, 0x3C003C00u, 0x3C003C00u, 0x3C003C00u);
        *reinterpret_cast<uint4*>(smc + VS_B(s) + row * FROWB + 128) = ones;
    }
    __syncthreads();

    unsigned qa[4][4];
    #pragma unroll
    for (int ks = 0; ks < 4; ++ks)
        LDSM_X4(qa[ks][0], qa[ks][1], qa[ks][2], qa[ks][3], qFrag + ks * 32);

    float m_i[2] = {-CUDART_INF_F, -CUDART_INF_F};
    float osum[4] = {0.0f, 0.0f, 0.0f, 0.0f};   // l accumulators via P*1 mma
    float o[8][4];
    #pragma unroll
    for (int ni = 0; ni < 8; ++ni)
        #pragma unroll
        for (int j = 0; j < 4; ++j) o[ni][j] = 0.0f;

    const int row_loc = warp * 16 + r;
    const int ktmax   = qt;               // 64-row q-tile == 64-row kv-tile

    for (int kt = 0; kt <= ktmax; ++kt) {
        const int s  = kt & 1;
        const int k0 = kt * 64;

        CP_WAIT(0);
        __syncthreads();
        if (kt < ktmax) load_kv(kt + 1, s ^ 1);

        // ---- S = Q K^T ----
        float sreg[8][4];
        #pragma unroll
        for (int ni = 0; ni < 8; ++ni)
            #pragma unroll
            for (int j = 0; j < 4; ++j) sreg[ni][j] = 0.0f;

        #pragma unroll
        for (int ks = 0; ks < 4; ++ks) {
            #pragma unroll
            for (int pi = 0; pi < 4; ++pi) {
                unsigned b0, b1, b2, b3;
                LDSM_X4(b0, b1, b2, b3, kF[s] + pi * (16 * FROWB) + ks * 32);
                mma_f16(sreg[2*pi],   qa[ks][0], qa[ks][1], qa[ks][2], qa[ks][3], b0, b1);
                mma_f16(sreg[2*pi+1], qa[ks][0], qa[ks][1], qa[ks][2], qa[ks][3], b2, b3);
            }
        }

        // ---- causal mask (diagonal tile only) ----
        if (kt == ktmax) {
            const int rg0 = q0 + row_loc;
            #pragma unroll
            for (int ni = 0; ni < 8; ++ni) {
                int cg = k0 + ni * 8 + 2 * t;
                if (cg     > rg0    ) sreg[ni][0] = -CUDART_INF_F;
                if (cg + 1 > rg0    ) sreg[ni][1] = -CUDART_INF_F;
                if (cg     > rg0 + 8) sreg[ni][2] = -CUDART_INF_F;
                if (cg + 1 > rg0 + 8) sreg[ni][3] = -CUDART_INF_F;
            }
        }

        // ---- running max + rescale (fp32) ----
        float mnew[2], alpha[2];
        #pragma unroll
        for (int hh = 0; hh < 2; ++hh) {
            float mx = -CUDART_INF_F;
            #pragma unroll
            for (int ni = 0; ni < 8; ++ni)
                mx = fmaxf(mx, fmaxf(sreg[ni][hh * 2], sreg[ni][hh * 2 + 1]));
            mx = fmaxf(mx, __shfl_xor_sync(0xffffffffu, mx, 1, 4));
            mx = fmaxf(mx, __shfl_xor_sync(0xffffffffu, mx, 2, 4));
            mnew[hh]  = fmaxf(m_i[hh], mx);
            alpha[hh] = ex2f(m_i[hh] - mnew[hh]);
            m_i[hh]   = mnew[hh];
            #pragma unroll
            for (int ni = 0; ni < 8; ++ni) {
                o[ni][hh * 2]     *= alpha[hh];
                o[ni][hh * 2 + 1] *= alpha[hh];
            }
        }
        osum[0] *= alpha[0]; osum[1] *= alpha[0];
        osum[2] *= alpha[1]; osum[3] *= alpha[1];

        // ---- p = 2^(s-m) -> A-fragments (fp32 ex2; l comes from P*1 mma) ----
        unsigned pa[4][4];
        #pragma unroll
        for (int ks = 0; ks < 4; ++ks) {
            #pragma unroll
            for (int half = 0; half < 2; ++half) {
                int ni = 2 * ks + half;
                float p0 = ex2f(sreg[ni][0] - mnew[0]);
                float p1 = ex2f(sreg[ni][1] - mnew[0]);
                float p2 = ex2f(sreg[ni][2] - mnew[1]);
                float p3 = ex2f(sreg[ni][3] - mnew[1]);
                pa[ks][2 * half]     = pack_h2(p0, p1);
                pa[ks][2 * half + 1] = pack_h2(p2, p3);
            }
        }

        // ---- O += P V, and osum += P * ones (l via tensor core) ----
        #pragma unroll
        for (int ks = 0; ks < 4; ++ks) {
            #pragma unroll
            for (int pi = 0; pi < 4; ++pi) {
                unsigned b0, b1, b2, b3;
                LDSM_X4T(b0, b1, b2, b3,
                         vF[s] + ks * (16 * FROWB) + pi * 32);
                mma_f16(o[2*pi],   pa[ks][0], pa[ks][1], pa[ks][2], pa[ks][3], b0, b1);
                mma_f16(o[2*pi+1], pa[ks][0], pa[ks][1], pa[ks][2], pa[ks][3], b2, b3);
            }
            unsigned sb0, sb1;
            LDSM_X2T(sb0, sb1, vS[s] + ks * (16 * FROWB));
            mma_f16(osum, pa[ks][0], pa[ks][1], pa[ks][2], pa[ks][3], sb0, sb1);
        }
        // no tail barrier: next iteration's top-of-loop sync provides ordering
    }

    // ---- normalize + fp16 store (l = osum; all cols of ones-block equal) ----
    const float inv_l0 = 1.0f / osum[0];
    const float inv_l1 = 1.0f / osum[2];
    #pragma unroll
    for (int hh = 0; hh < 2; ++hh) {
        float inv_l = (hh == 0) ? inv_l0 : inv_l1;
        int row = q0 + row_loc + hh * 8;
        #pragma unroll
        for (int ni = 0; ni < 8; ++ni) {
            *reinterpret_cast<__half2*>(
                &O[base + (size_t)row * DIM + ni * 8 + 2 * t]) =
                __floats2half2_rn(o[ni][hh * 2] * inv_l, o[ni][hh * 2 + 1] * inv_l);
        }
    }
}

// ---------------------------------------------------------------------------
// Launch
// ---------------------------------------------------------------------------
extern "C" void kernel_launch(void* const* d_in, const int* in_sizes, int n_in,
                              void* d_out, int out_size)
{
    const float* x  = (const float*)d_in[0];
    const float* Wq = (const float*)d_in[2];
    const float* Wk = (const float*)d_in[3];
    const float* Wv = (const float*)d_in[4];
    const float* Wo = (const float*)d_in[5];
    float* out = (float*)d_out;

    __half *QKV, *AOd, *Xh, *Wh;
    cudaGetSymbolAddress((void**)&QKV, g_QKV);
    cudaGetSymbolAddress((void**)&AOd, g_AO);
    cudaGetSymbolAddress((void**)&Xh,  g_Xh);
    cudaGetSymbolAddress((void**)&Wh,  g_Wh);

    static bool attr_set = false;
    if (!attr_set) {
        cudaFuncSetAttribute(flash_f16,
                             cudaFuncAttributeMaxDynamicSharedMemorySize, FL_SMEMB);
        cudaFuncSetAttribute((gemm_f16<true, true>),
                             cudaFuncAttributeMaxDynamicSharedMemorySize, SMEM_GEMM);
        cudaFuncSetAttribute((gemm_f16<false, false>),
                             cudaFuncAttributeMaxDynamicSharedMemorySize, SMEM_GEMM);
        attr_set = true;
    }

    // fused fp32->fp16 conversion of x + all weights, MLP=4, exact division
    cvt_all<<<1536, 256>>>((const float4*)x,
                           (const float4*)Wq, (const float4*)Wk,
                           (const float4*)Wv, (const float4*)Wo,
                           (__half2*)Xh, (__half2*)Wh);

    // fused Q,K,V projections; Q pre-scaled by 0.125*log2(e)
    dim3 gQKV(DIM / 128, MTOT / 128, 3);   // (8, 64, 3)
    gemm_f16<true, true><<<gQKV, 256, SMEM_GEMM>>>(Xh, Wh, QKV);

    const __half* Qd = QKV;
    const __half* Kd = QKV + (size_t)MTOT * DIM;
    const __half* Vd = QKV + 2 * (size_t)MTOT * DIM;

    dim3 gF(SEQ / 64, NHEAD, BATCH);       // (32, 16, 4)
    flash_f16<<<gF, 128, FL_SMEMB>>>(Qd, Kd, Vd, AOd);

    dim3 gO(DIM / 128, MTOT / 128, 1);     // (8, 64, 1)
    gemm_f16<false, false><<<gO, 256, SMEM_GEMM>>>(AOd, Wh + 3 * (size_t)DIM * DIM, out);
}